// round 1
// baseline (speedup 1.0000x reference)
#include <cuda_runtime.h>
#include <math.h>

// Problem constants: x (8, 64, 256, 256) fp32, conv_w (64,64,3), conv_b (64)
// out (8, 64, 256, 256) fp32.
//
// Reformulation: out_o = z0 + z1 M1^T + z2 M2^T
//                + (M1 (z1 a0)) a7^T + (M1 (z2 a0)) a6^T + (M1 (z2 a1)) a7^T
//                + b_o g g^T
// per 8x8 spatial block, where z_k = sum_i W[o,i,k] x_i (pointwise channel mix),
// M1 = D^T U D, M2 = D^T U^2 D (U = 8x8 superdiagonal shift), a_k = row k of D,
// a0 = const 1/sqrt(8), g = column sums of D.

#define SM_FLOATS 43040   // 16384 (Xs) + 12288 (Wall) + 12672 (Zbuf) + 1536 (Tsum) + 160 (consts)

__device__ float c_all[160];  // [0:64) M1, [64:128) M2, [128:136) a1, [136:144) a6, [144:152) a7, [152:160) g

__global__ void init_consts_kernel() {
    if (threadIdx.x != 0 || blockIdx.x != 0) return;
    const double PI = 3.14159265358979323846;
    double D[8][8];
    for (int k = 0; k < 8; k++)
        for (int n = 0; n < 8; n++) {
            double v = 0.5 * cos(PI * (2.0 * n + 1.0) * (double)k / 16.0); // sqrt(2/8)=0.5
            if (k == 0) v *= 0.7071067811865476;
            D[k][n] = v;
        }
    for (int p = 0; p < 8; p++)
        for (int q = 0; q < 8; q++) {
            double m1 = 0.0, m2 = 0.0;
            for (int n = 0; n < 7; n++) m1 += D[n][p] * D[n + 1][q];
            for (int n = 0; n < 6; n++) m2 += D[n][p] * D[n + 2][q];
            c_all[p * 8 + q]      = (float)m1;
            c_all[64 + p * 8 + q] = (float)m2;
        }
    for (int n = 0; n < 8; n++) {
        c_all[128 + n] = (float)D[1][n];
        c_all[136 + n] = (float)D[6][n];
        c_all[144 + n] = (float)D[7][n];
        double g = 0.0;
        for (int k = 0; k < 8; k++) g += D[k][n];
        c_all[152 + n] = (float)g;
    }
}

// One CTA: batch b, block-row by, 4 horizontal 8x8 blocks (8 rows x 32 cols), all 64 channels.
__global__ void __launch_bounds__(256) dctconv_fused(
    const float* __restrict__ x,
    const float* __restrict__ cw,
    const float* __restrict__ cb,
    float* __restrict__ out)
{
    extern __shared__ float sm[];
    float* Xs   = sm;             // [64][256]  input tile, px = r*32 + c
    float* Wall = sm + 16384;     // [64][192]  Wall[i*192 + o*3 + kk] = w[o][i][kk]
    float* Zbuf = sm + 28672;     // [48][264]  z rows for one group of 16 out-channels
    float* Tsum = sm + 41344;     // [16][4][3][8]
    float* sC   = sm + 42880;     // [160] constants

    const int tid = threadIdx.x;
    const int y0 = blockIdx.y * 8;
    const int x0 = blockIdx.x * 32;
    const size_t bb = blockIdx.z;

    if (tid < 160) sC[tid] = c_all[tid];

    // ---- load X tile (coalesced float4) ----
    const float* xb = x + bb * (size_t)(64 * 65536);
    for (int v = tid; v < 4096; v += 256) {
        int i = v >> 6;
        int rem = v & 63;
        int r = rem >> 3;
        int f = rem & 7;
        *(float4*)(Xs + i * 256 + r * 32 + f * 4) =
            *(const float4*)(xb + (size_t)i * 65536 + (y0 + r) * 256 + x0 + f * 4);
    }
    // ---- load W into [i][j=o*3+kk] layout (hits L2; W is only 48 KB total) ----
    for (int v = tid; v < 12288; v += 256) {
        int i = v / 192;
        int j = v - i * 192;
        int o = j / 3;
        int kk = j - o * 3;
        Wall[v] = cw[(o * 64 + i) * 3 + kk];
    }
    __syncthreads();

    const float* sM1 = sC;
    const float* sM2 = sC + 64;
    const float* sA1 = sC + 128;
    const float* sA6 = sC + 136;
    const float* sA7 = sC + 144;
    const float* sG  = sC + 152;

    const int rb = tid >> 5;   // 0..7  : owns z-rows rb*6..rb*6+5
    const int pb = tid & 31;   // 0..31 : owns pixel pairs pb, pb+32, pb+64, pb+96

    for (int og = 0; og < 4; og++) {
        // ---- Phase A: channel mix, z[j][p] = sum_i Wall[i][og*48+j] * Xs[i][p] ----
        {
            unsigned long long acc[6][4];
            #pragma unroll
            for (int s = 0; s < 6; s++)
                #pragma unroll
                for (int q = 0; q < 4; q++) acc[s][q] = 0ull;

            const float* Wp = Wall + og * 48 + rb * 6;
            #pragma unroll 4
            for (int i = 0; i < 64; i++) {
                unsigned long long xv[4];
                const float* xrow = Xs + i * 256 + 2 * pb;
                #pragma unroll
                for (int q = 0; q < 4; q++)
                    xv[q] = *(const unsigned long long*)(xrow + 64 * q);
                const float* wrow = Wp + i * 192;
                #pragma unroll
                for (int s = 0; s < 6; s++) {
                    unsigned long long w2;
                    asm("mov.b64 %0, {%1, %1};" : "=l"(w2) : "r"(__float_as_uint(wrow[s])));
                    #pragma unroll
                    for (int q = 0; q < 4; q++)
                        asm("fma.rn.f32x2 %0, %1, %2, %0;"
                            : "+l"(acc[s][q]) : "l"(w2), "l"(xv[q]));
                }
            }
            #pragma unroll
            for (int s = 0; s < 6; s++) {
                float* zr = Zbuf + (rb * 6 + s) * 264 + 2 * pb;
                #pragma unroll
                for (int q = 0; q < 4; q++)
                    *(unsigned long long*)(zr + 64 * q) = acc[s][q];
            }
        }
        __syncthreads();

        // ---- Tsum: per (u=o_sub, B=block) row sums of z1, z2 and dot(z2, a1) ----
        #pragma unroll
        for (int vv = 0; vv < 6; vv++) {
            int v = tid + 256 * vv;       // 1536 values
            int s = v & 7;
            int t = v >> 3;
            int which = t % 3;
            int ub = t / 3;
            int B = ub & 3;
            int u = ub >> 2;
            int jrow = u * 3 + ((which == 0) ? 1 : 2);
            const float* zr = Zbuf + jrow * 264 + s * 32 + B * 8;
            float acc = 0.f;
            if (which == 2) {
                #pragma unroll
                for (int m = 0; m < 8; m++) acc += zr[m] * sA1[m];
            } else {
                #pragma unroll
                for (int m = 0; m < 8; m++) acc += zr[m];
            }
            Tsum[v] = acc;
        }
        __syncthreads();

        // ---- Phase B: spatial epilogue per (out-channel, block), 4 threads per unit ----
        {
            const int u  = tid >> 4;        // 0..15
            const int B  = (tid >> 2) & 3;  // 0..3
            const int rp = tid & 3;         // rows 2rp, 2rp+1
            const float* z0p = Zbuf + (u * 3) * 264 + B * 8;
            const float* ts = Tsum + (u * 4 + B) * 24;
            const int o = og * 16 + u;
            const float bias = cb[o];
            float* outp = out + (bb * 64 + o) * (size_t)65536 + (size_t)y0 * 256 + x0 + B * 8;

            #pragma unroll
            for (int rr = 0; rr < 2; rr++) {
                const int r = rp * 2 + rr;
                float a[8], z1r[8], z2r[8];
                #pragma unroll
                for (int m = 0; m < 8; m++) {
                    a[m]   = z0p[r * 32 + m];
                    z1r[m] = z0p[264 + r * 32 + m];
                    z2r[m] = z0p[528 + r * 32 + m];
                }
                float w1 = 0.f, w2 = 0.f, w3 = 0.f;
                #pragma unroll
                for (int s = 0; s < 8; s++) {
                    float m1 = sM1[r * 8 + s];
                    w1 += m1 * ts[s];
                    w2 += m1 * ts[8 + s];
                    w3 += m1 * ts[16 + s];
                }
                const float inv_s8 = 0.3535533905932738f;  // 1/sqrt(8) = a0 entries
                const float wa7 = w1 * inv_s8 + w3;
                const float wa6 = w2 * inv_s8;
                const float gb  = bias * sG[r];
                #pragma unroll
                for (int c = 0; c < 8; c++) {
                    float v = a[c];
                    #pragma unroll
                    for (int m = 0; m < 8; m++) v += z1r[m] * sM1[c * 8 + m];
                    #pragma unroll
                    for (int m = 0; m < 8; m++) v += z2r[m] * sM2[c * 8 + m];
                    v += wa7 * sA7[c] + wa6 * sA6[c] + gb * sG[c];
                    a[c] = v;
                }
                *(float4*)(outp + r * 256)     = make_float4(a[0], a[1], a[2], a[3]);
                *(float4*)(outp + r * 256 + 4) = make_float4(a[4], a[5], a[6], a[7]);
            }
        }
        __syncthreads();
    }
}

extern "C" void kernel_launch(void* const* d_in, const int* in_sizes, int n_in,
                              void* d_out, int out_size) {
    const float* x  = (const float*)d_in[0];
    const float* cw = (const float*)d_in[1];
    const float* cb = (const float*)d_in[2];
    float* out = (float*)d_out;
    (void)in_sizes; (void)n_in; (void)out_size;

    cudaFuncSetAttribute(dctconv_fused, cudaFuncAttributeMaxDynamicSharedMemorySize,
                         SM_FLOATS * (int)sizeof(float));

    init_consts_kernel<<<1, 1>>>();
    dim3 grid(8, 32, 8);   // (nW/4, nH, bsz)
    dctconv_fused<<<grid, 256, SM_FLOATS * sizeof(float)>>>(x, cw, cb, out);
}

// round 2
// speedup vs baseline: 1.5008x; 1.5008x over previous
#include <cuda_runtime.h>
#include <math.h>

// x (8,64,256,256) fp32, conv_w (64,64,3), conv_b (64) -> out (8,64,256,256) fp32
//
// out_o = z0 + z1 M1^T + z2 M2^T
//       + (M1 (z1 a0)) a7^T + (M1 (z2 a0)) a6^T + (M1 (z2 a1)) a7^T + b_o g g^T
// per 8x8 block; z_k = sum_i W[o,i,k] x_i; M1=D^T U D, M2=D^T U^2 D.

typedef unsigned long long ull;

__device__ float c_all[160];  // [0:64) M1, [64:128) M2, [128:136) a1, [136:144) a6, [144:152) a7, [152:160) g

__device__ double Dkn(int k, int n) {
    const double PI = 3.14159265358979323846;
    double v = 0.5 * cos(PI * (2.0 * n + 1.0) * (double)k / 16.0);
    if (k == 0) v *= 0.7071067811865476;
    return v;
}

__global__ void init_consts_kernel() {
    int t = threadIdx.x;
    if (t >= 160) return;
    double r = 0.0;
    if (t < 64) {
        int p = t >> 3, q = t & 7;
        for (int n = 0; n < 7; n++) r += Dkn(n, p) * Dkn(n + 1, q);
    } else if (t < 128) {
        int s = t - 64; int p = s >> 3, q = s & 7;
        for (int n = 0; n < 6; n++) r += Dkn(n, p) * Dkn(n + 2, q);
    } else if (t < 136) r = Dkn(1, t - 128);
    else if (t < 144)   r = Dkn(6, t - 136);
    else if (t < 152)   r = Dkn(7, t - 144);
    else {
        int n = t - 152;
        for (int k = 0; k < 8; k++) r += Dkn(k, n);
    }
    c_all[t] = (float)r;
}

// smem layout (floats)
#define XS_OFF 0            // [64][256], px = B*64 + r*8 + c (block-major)
#define WG_OFF 16384        // [64][48]   Wg[i*48 + (u*3+kk)] = w[og*16+u][i][kk]
#define ZB_OFF 19456        // [48][132]  z rows for one 2-block chunk
#define TS_OFF 25792        // [32][24]   (u*2+Bl)*24 + which*8 + s
#define SC_OFF 26560        // [160]
#define SM_FLOATS 26720     // 106880 B -> 2 CTAs/SM

__global__ void __launch_bounds__(256, 2) dctconv_fused(
    const float* __restrict__ x,
    const float* __restrict__ cw,
    const float* __restrict__ cb,
    float* __restrict__ out)
{
    extern __shared__ float sm[];
    float* Xs = sm + XS_OFF;
    float* Wg = sm + WG_OFF;
    float* Zb = sm + ZB_OFF;
    float* Ts = sm + TS_OFF;
    float* sC = sm + SC_OFF;

    const int tid = threadIdx.x;
    const int y0 = blockIdx.y * 8;
    const int x0 = blockIdx.x * 32;
    const size_t bb = blockIdx.z;

    if (tid < 160) sC[tid] = c_all[tid];

    // ---- load X tile, block-major smem layout, conflict-free STS.128 ----
    const float* xb = x + bb * (size_t)(64 * 65536);
    #pragma unroll
    for (int k = 0; k < 16; k++) {
        int v = tid + 256 * k;
        int i = v >> 6;
        int rem = v & 63;
        int B = (rem >> 4) & 3;
        int r = (rem >> 1) & 7;
        int c4 = (rem & 1) * 4;
        *(float4*)(Xs + i * 256 + B * 64 + r * 8 + c4) =
            *(const float4*)(xb + (size_t)i * 65536 + (y0 + r) * 256 + x0 + B * 8 + c4);
    }

    const float* sM1 = sC;
    const float* sM2 = sC + 64;
    const float* sA1 = sC + 128;
    const float* sA6 = sC + 136;
    const float* sA7 = sC + 144;
    const float* sG  = sC + 152;

    const int rb = tid >> 5;   // 0..7 : owns z-rows rb*6..rb*6+5
    const int pt = tid & 31;   // 0..31: owns pixel pairs pt, pt+32 (within 128-px chunk)

    for (int og = 0; og < 4; og++) {
        __syncthreads();
        // ---- load this group's W slice: Wg[i][u*3+kk] ----
        for (int v = tid; v < 3072; v += 256) {
            int i = v / 48;
            int j = v - i * 48;
            int u = j / 3;
            int kk = j - u * 3;
            Wg[v] = cw[((og * 16 + u) * 64 + i) * 3 + kk];
        }
        __syncthreads();

        for (int ch = 0; ch < 2; ch++) {
            // ---- Phase A: z[j][p] = sum_i Wg[i][j] * Xs[i][ch*128+p] ----
            {
                ull acc[6][2];
                #pragma unroll
                for (int s = 0; s < 6; s++) { acc[s][0] = 0ull; acc[s][1] = 0ull; }

                const float* xp = Xs + ch * 128 + 2 * pt;
                const float* wp = Wg + rb * 6;
                #pragma unroll 8
                for (int i = 0; i < 64; i++) {
                    ull xv0 = *(const ull*)(xp + i * 256);
                    ull xv1 = *(const ull*)(xp + i * 256 + 64);
                    const float* wr = wp + i * 48;
                    #pragma unroll
                    for (int s = 0; s < 6; s++) {
                        ull w2;
                        asm("mov.b64 %0, {%1, %1};" : "=l"(w2) : "r"(__float_as_uint(wr[s])));
                        asm("fma.rn.f32x2 %0, %1, %2, %0;" : "+l"(acc[s][0]) : "l"(w2), "l"(xv0));
                        asm("fma.rn.f32x2 %0, %1, %2, %0;" : "+l"(acc[s][1]) : "l"(w2), "l"(xv1));
                    }
                }
                #pragma unroll
                for (int s = 0; s < 6; s++) {
                    float* zr = Zb + (rb * 6 + s) * 132 + 2 * pt;
                    *(ull*)zr        = acc[s][0];
                    *(ull*)(zr + 64) = acc[s][1];
                }
            }
            __syncthreads();

            // ---- Tsum: per (u, Bl): which=0: row-sums z1; 1: row-sums z2; 2: dot(z2 rows, a1) ----
            #pragma unroll
            for (int vv = 0; vv < 3; vv++) {
                int v = tid + 256 * vv;     // 768 values
                int s = v & 7;
                int t2 = v >> 3;
                int which = t2 % 3;
                int ub = t2 / 3;            // u*2+Bl
                int jrow = (ub >> 1) * 3 + ((which == 0) ? 1 : 2);
                const float* zr = Zb + jrow * 132 + (ub & 1) * 64 + s * 8;
                float a = 0.f;
                if (which == 2) {
                    #pragma unroll
                    for (int m = 0; m < 8; m++) a += zr[m] * sA1[m];
                } else {
                    #pragma unroll
                    for (int m = 0; m < 8; m++) a += zr[m];
                }
                Ts[ub * 24 + which * 8 + s] = a;
            }
            __syncthreads();

            // ---- Phase B: spatial epilogue, 1 thread = 1 (out-ch, block, row) ----
            {
                const int u  = tid >> 4;        // 0..15
                const int Bl = (tid >> 3) & 1;  // 0..1
                const int r  = tid & 7;         // 0..7
                const float* z0r = Zb + (u * 3) * 132 + Bl * 64 + r * 8;
                const float* z1r = z0r + 132;
                const float* z2r = z0r + 264;
                const float* ts  = Ts + (u * 2 + Bl) * 24;
                const int o = og * 16 + u;
                const float bias = __ldg(cb + o);

                float w1 = 0.f, w2 = 0.f, w3 = 0.f;
                #pragma unroll
                for (int s = 0; s < 8; s++) {
                    float m1 = sM1[r * 8 + s];
                    w1 += m1 * ts[s];
                    w2 += m1 * ts[8 + s];
                    w3 += m1 * ts[16 + s];
                }
                const float inv_s8 = 0.3535533905932738f;  // 1/sqrt(8)
                const float wa7 = w1 * inv_s8 + w3;
                const float wa6 = w2 * inv_s8;
                const float gb  = bias * sG[r];

                float a[8];
                #pragma unroll
                for (int c = 0; c < 8; c++)
                    a[c] = z0r[c] + wa7 * sA7[c] + wa6 * sA6[c] + gb * sG[c];
                #pragma unroll
                for (int m = 0; m < 8; m++) {
                    float z1v = z1r[m], z2v = z2r[m];
                    #pragma unroll
                    for (int c = 0; c < 8; c++)
                        a[c] += z1v * sM1[c * 8 + m] + z2v * sM2[c * 8 + m];
                }

                const int Bg = ch * 2 + Bl;
                float* outp = out + (bb * 64 + o) * (size_t)65536
                                  + (size_t)(y0 + r) * 256 + x0 + Bg * 8;
                *(float4*)outp       = make_float4(a[0], a[1], a[2], a[3]);
                *(float4*)(outp + 4) = make_float4(a[4], a[5], a[6], a[7]);
            }
            __syncthreads();
        }
    }
}

extern "C" void kernel_launch(void* const* d_in, const int* in_sizes, int n_in,
                              void* d_out, int out_size) {
    const float* x  = (const float*)d_in[0];
    const float* cw = (const float*)d_in[1];
    const float* cb = (const float*)d_in[2];
    float* out = (float*)d_out;
    (void)in_sizes; (void)n_in; (void)out_size;

    cudaFuncSetAttribute(dctconv_fused, cudaFuncAttributeMaxDynamicSharedMemorySize,
                         SM_FLOATS * (int)sizeof(float));

    init_consts_kernel<<<1, 192>>>();
    dim3 grid(8, 32, 8);   // (W/32, H/8, bsz)
    dctconv_fused<<<grid, 256, SM_FLOATS * sizeof(float)>>>(x, cw, cb, out);
}

// round 3
// speedup vs baseline: 1.5628x; 1.0413x over previous
#include <cuda_runtime.h>
#include <math.h>

// x (8,64,256,256) fp32, conv_w (64,64,3), conv_b (64) -> out (8,64,256,256) fp32
//
// out_o = z0 + z1 M1^T + z2 M2^T
//       + (M1 (z1 a0)) a7^T + (M1 (z2 a0)) a6^T + (M1 (z2 a1)) a7^T + b_o g g^T
// per 8x8 block; z_k = sum_i W[o,i,k] x_i; M1=D^T U D, M2=D^T U^2 D.

typedef unsigned long long ull;

__device__ float c_all[160];  // [0:64) M1, [64:128) M2, [128:136) a1, [136:144) a6, [144:152) a7, [152:160) g

__device__ double Dkn(int k, int n) {
    const double PI = 3.14159265358979323846;
    double v = 0.5 * cos(PI * (2.0 * n + 1.0) * (double)k / 16.0);
    if (k == 0) v *= 0.7071067811865476;
    return v;
}

__global__ void init_consts_kernel() {
    int t = threadIdx.x;
    if (t >= 160) return;
    double r = 0.0;
    if (t < 64) {
        int p = t >> 3, q = t & 7;
        for (int n = 0; n < 7; n++) r += Dkn(n, p) * Dkn(n + 1, q);
    } else if (t < 128) {
        int s = t - 64; int p = s >> 3, q = s & 7;
        for (int n = 0; n < 6; n++) r += Dkn(n, p) * Dkn(n + 2, q);
    } else if (t < 136) r = Dkn(1, t - 128);
    else if (t < 144)   r = Dkn(6, t - 136);
    else if (t < 152)   r = Dkn(7, t - 144);
    else {
        int n = t - 152;
        for (int k = 0; k < 8; k++) r += Dkn(k, n);
    }
    c_all[t] = (float)r;
}

// smem layout (floats)
#define XS_OFF 0            // [64][256], px = B*64 + r*8 + c (block-major)
#define WG_OFF 16384        // [8][64][8]  Wg[(rb*64+i)*8 + s] = w-group slice (s<6 used)
#define ZB_OFF 20480        // [48][132]   z rows for one 2-block (128 px) chunk
#define TS_OFF 26816        // [32][24]
#define SC_OFF 27584        // [160]
#define SM_FLOATS 27744     // 110976 B -> 2 CTAs/SM

__global__ void __launch_bounds__(256, 2) dctconv_fused(
    const float* __restrict__ x,
    const float* __restrict__ cw,
    const float* __restrict__ cb,
    float* __restrict__ out)
{
    extern __shared__ float sm[];
    float* Xs = sm + XS_OFF;
    float* Wg = sm + WG_OFF;
    float* Zb = sm + ZB_OFF;
    float* Ts = sm + TS_OFF;
    float* sC = sm + SC_OFF;

    const int tid = threadIdx.x;
    const int y0 = blockIdx.y * 8;
    const int x0 = blockIdx.x * 32;
    const size_t bb = blockIdx.z;

    if (tid < 160) sC[tid] = c_all[tid];

    // ---- load X tile, block-major smem layout (px = B*64 + r*8 + c) ----
    const float* xb = x + bb * (size_t)(64 * 65536);
    #pragma unroll
    for (int k = 0; k < 16; k++) {
        int v = tid + 256 * k;
        int i = v >> 6;
        int rem = v & 63;
        int B = (rem >> 4) & 3;
        int r = (rem >> 1) & 7;
        int c4 = (rem & 1) * 4;
        *(float4*)(Xs + i * 256 + B * 64 + r * 8 + c4) =
            *(const float4*)(xb + (size_t)i * 65536 + (y0 + r) * 256 + x0 + B * 8 + c4);
    }

    const float* sM1 = sC;
    const float* sM2 = sC + 64;
    const float* sA1 = sC + 128;
    const float* sA6 = sC + 136;
    const float* sA7 = sC + 144;
    const float* sG  = sC + 152;

    const int rb = tid >> 5;   // 0..7 : owns z-rows rb*6..rb*6+5
    const int pt = tid & 31;   // 0..31: owns pixels 4pt..4pt+3 of the 128-px chunk

    for (int og = 0; og < 4; og++) {
        __syncthreads();
        // ---- load group W slice: Wg[(rb*64+i)*8 + s], s = 0..5 ----
        for (int v = tid; v < 3072; v += 256) {
            int s = v % 6;
            int t2 = v / 6;
            int i = t2 & 63;
            int rbw = t2 >> 6;
            int j = rbw * 6 + s;        // 0..47
            int u = j / 3;
            int kk = j - u * 3;
            Wg[(rbw * 64 + i) * 8 + s] = cw[((og * 16 + u) * 64 + i) * 3 + kk];
        }
        __syncthreads();

        for (int ch = 0; ch < 2; ch++) {
            // ---- Phase A: z[j][p] = sum_i Wg[rb][i][j-rb*6] * Xs[i][ch*128+p] ----
            {
                ull acc[6][2];
                #pragma unroll
                for (int s = 0; s < 6; s++) { acc[s][0] = 0ull; acc[s][1] = 0ull; }

                const float* xp = Xs + ch * 128 + 4 * pt;
                const float* wp = Wg + rb * 512;
                #pragma unroll 8
                for (int i = 0; i < 64; i++) {
                    ulonglong2 xv = *(const ulonglong2*)(xp + i * 256);   // LDS.128
                    float4 wv  = *(const float4*)(wp + i * 8);            // broadcast LDS.128
                    float2 wv2 = *(const float2*)(wp + i * 8 + 4);        // broadcast LDS.64
                    float ws[6] = {wv.x, wv.y, wv.z, wv.w, wv2.x, wv2.y};
                    #pragma unroll
                    for (int s = 0; s < 6; s++) {
                        ull w2;
                        asm("mov.b64 %0, {%1, %1};" : "=l"(w2) : "r"(__float_as_uint(ws[s])));
                        asm("fma.rn.f32x2 %0, %1, %2, %0;" : "+l"(acc[s][0]) : "l"(w2), "l"(xv.x));
                        asm("fma.rn.f32x2 %0, %1, %2, %0;" : "+l"(acc[s][1]) : "l"(w2), "l"(xv.y));
                    }
                }
                #pragma unroll
                for (int s = 0; s < 6; s++) {
                    ulonglong2 st; st.x = acc[s][0]; st.y = acc[s][1];
                    *(ulonglong2*)(Zb + (rb * 6 + s) * 132 + 4 * pt) = st;  // STS.128
                }
            }
            __syncthreads();

            // ---- Tsum: per (u, Bl): 0: row-sums z1; 1: row-sums z2; 2: dot(z2 rows, a1) ----
            #pragma unroll
            for (int vv = 0; vv < 3; vv++) {
                int v = tid + 256 * vv;     // 768 values
                int s = v & 7;
                int t2 = v >> 3;
                int which = t2 % 3;
                int ub = t2 / 3;            // u*2+Bl
                int jrow = (ub >> 1) * 3 + ((which == 0) ? 1 : 2);
                const float* zr = Zb + jrow * 132 + (ub & 1) * 64 + s * 8;
                float a = 0.f;
                if (which == 2) {
                    #pragma unroll
                    for (int m = 0; m < 8; m++) a += zr[m] * sA1[m];
                } else {
                    #pragma unroll
                    for (int m = 0; m < 8; m++) a += zr[m];
                }
                Ts[ub * 24 + which * 8 + s] = a;
            }
            __syncthreads();

            // ---- Phase B: spatial epilogue, 1 thread = 1 (out-ch, block, row) ----
            {
                const int u  = tid >> 4;        // 0..15
                const int Bl = (tid >> 3) & 1;  // 0..1
                const int r  = tid & 7;         // 0..7
                const float* z0r = Zb + (u * 3) * 132 + Bl * 64 + r * 8;
                const float* z1r = z0r + 132;
                const float* z2r = z0r + 264;
                const float* ts  = Ts + (u * 2 + Bl) * 24;
                const int o = og * 16 + u;
                const float bias = __ldg(cb + o);

                float w1 = 0.f, w2 = 0.f, w3 = 0.f;
                #pragma unroll
                for (int s = 0; s < 8; s++) {
                    float m1 = sM1[r * 8 + s];
                    w1 += m1 * ts[s];
                    w2 += m1 * ts[8 + s];
                    w3 += m1 * ts[16 + s];
                }
                const float inv_s8 = 0.3535533905932738f;  // 1/sqrt(8)
                const float wa7 = w1 * inv_s8 + w3;
                const float wa6 = w2 * inv_s8;
                const float gb  = bias * sG[r];

                float a[8];
                #pragma unroll
                for (int c = 0; c < 8; c++)
                    a[c] = z0r[c] + wa7 * sA7[c] + wa6 * sA6[c] + gb * sG[c];
                #pragma unroll
                for (int m = 0; m < 8; m++) {
                    float z1v = z1r[m], z2v = z2r[m];
                    #pragma unroll
                    for (int c = 0; c < 8; c++)
                        a[c] += z1v * sM1[c * 8 + m] + z2v * sM2[c * 8 + m];
                }

                const int Bg = ch * 2 + Bl;
                float* outp = out + (bb * 64 + o) * (size_t)65536
                                  + (size_t)(y0 + r) * 256 + x0 + Bg * 8;
                *(float4*)outp       = make_float4(a[0], a[1], a[2], a[3]);
                *(float4*)(outp + 4) = make_float4(a[4], a[5], a[6], a[7]);
            }
            __syncthreads();
        }
    }
}

extern "C" void kernel_launch(void* const* d_in, const int* in_sizes, int n_in,
                              void* d_out, int out_size) {
    const float* x  = (const float*)d_in[0];
    const float* cw = (const float*)d_in[1];
    const float* cb = (const float*)d_in[2];
    float* out = (float*)d_out;
    (void)in_sizes; (void)n_in; (void)out_size;

    cudaFuncSetAttribute(dctconv_fused, cudaFuncAttributeMaxDynamicSharedMemorySize,
                         SM_FLOATS * (int)sizeof(float));

    init_consts_kernel<<<1, 192>>>();
    dim3 grid(8, 32, 8);   // (W/32, H/8, bsz)
    dctconv_fused<<<grid, 256, SM_FLOATS * sizeof(float)>>>(x, cw, cb, out);
}

// round 5
// speedup vs baseline: 2.4111x; 1.5428x over previous
#include <cuda_runtime.h>
#include <math.h>

// x (8,64,256,256) fp32, conv_w (64,64,3), conv_b (64) -> out (8,64,256,256) fp32
// out_o = z0 + z1 M1^T + z2 M2^T
//       + (M1 (z1 a0)) a7^T + (M1 (z2 a0)) a6^T + (M1 (z2 a1)) a7^T + b_o g g^T
// z[px][j=o*3+kk] = sum_ch X[px][ch] W[j][ch], computed with mma.sync tf32 m16n8k8.

typedef unsigned int u32;

__device__ float c_all[160];  // [0:64) M1, [64:128) M2, [128:136) a1, [136:144) a6, [144:152) a7, [152:160) g

__device__ double Dkn(int k, int n) {
    const double PI = 3.14159265358979323846;
    double v = 0.5 * cos(PI * (2.0 * n + 1.0) * (double)k / 16.0);
    if (k == 0) v *= 0.7071067811865476;
    return v;
}

__global__ void init_consts_kernel() {
    int t = threadIdx.x;
    if (t >= 160) return;
    double r = 0.0;
    if (t < 64) {
        int p = t >> 3, q = t & 7;
        for (int n = 0; n < 7; n++) r += Dkn(n, p) * Dkn(n + 1, q);
    } else if (t < 128) {
        int s = t - 64; int p = s >> 3, q = s & 7;
        for (int n = 0; n < 6; n++) r += Dkn(n, p) * Dkn(n + 2, q);
    } else if (t < 136) r = Dkn(1, t - 128);
    else if (t < 144)   r = Dkn(6, t - 136);
    else if (t < 152)   r = Dkn(7, t - 144);
    else {
        int n = t - 152;
        for (int k = 0; k < 8; k++) r += Dkn(k, n);
    }
    c_all[t] = (float)r;
}

// smem float offsets
#define XS_F 0                       // Xs2[64 ch][264] (px 0..255), stride 264 (== 8 mod 32)
#define WT_F (64 * 264)              // Wt[64 ch][200]  (j 0..191), stride 200 (== 8 mod 32)
#define ZB_F (WT_F + 64 * 200)       // Zb[48 jl][268]  (px 0..255), stride 268
#define TS_F (ZB_F + 48 * 268)       // Ts[64 ub][24]
#define SC_F (TS_F + 64 * 24)        // consts [160]
#define SM_FLOATS (SC_F + 160)       // 44,256 floats = 177,024 B -> 1 CTA/SM

__device__ __forceinline__ float tf32r(float f) {
    u32 r;
    asm("cvt.rna.tf32.f32 %0, %1;" : "=r"(r) : "f"(f));
    return __uint_as_float(r);
}

__device__ __forceinline__ void mma_tf32(float* d, const float* a, const float* b) {
    asm volatile(
        "mma.sync.aligned.m16n8k8.row.col.f32.tf32.tf32.f32 "
        "{%0,%1,%2,%3}, {%4,%5,%6,%7}, {%8,%9}, {%0,%1,%2,%3};"
        : "+f"(d[0]), "+f"(d[1]), "+f"(d[2]), "+f"(d[3])
        : "r"(__float_as_uint(a[0])), "r"(__float_as_uint(a[1])),
          "r"(__float_as_uint(a[2])), "r"(__float_as_uint(a[3])),
          "r"(__float_as_uint(b[0])), "r"(__float_as_uint(b[1])));
}

__device__ __forceinline__ float dot4(float4 a, float4 b) {
    return a.x * b.x + a.y * b.y + a.z * b.z + a.w * b.w;
}

__global__ void __launch_bounds__(256) dctconv_mma(
    const float* __restrict__ x,
    const float* __restrict__ cw,
    const float* __restrict__ cb,
    float* __restrict__ out)
{
    extern __shared__ float sm[];
    float* Xs2 = sm + XS_F;
    float* Wt  = sm + WT_F;
    float* Zb  = sm + ZB_F;
    float* Ts  = sm + TS_F;
    float* sC  = sm + SC_F;

    const int tid = threadIdx.x;
    const int wid = tid >> 5;
    const int lane = tid & 31;
    const int g = lane >> 2;     // 0..7
    const int c = lane & 3;      // 0..3
    const int y0 = blockIdx.y * 8;
    const int x0 = blockIdx.x * 32;
    const size_t bb = blockIdx.z;

    if (tid < 160) sC[tid] = c_all[tid];

    // ---- stage X: Xs2[ch][px], px = B*64 + r*8 + cc (block-major), tf32-rounded ----
    const float* xb = x + bb * (size_t)(64 * 65536);
    #pragma unroll
    for (int k = 0; k < 16; k++) {
        int v = tid + 256 * k;
        int i = v >> 6, q = v & 63;
        int r = q >> 3, h = q & 7;
        float4 t = *(const float4*)(xb + (size_t)i * 65536 + (y0 + r) * 256 + x0 + h * 4);
        t.x = tf32r(t.x); t.y = tf32r(t.y); t.z = tf32r(t.z); t.w = tf32r(t.w);
        int pxb = (h >> 1) * 64 + r * 8 + 4 * (h & 1);
        *(float4*)(Xs2 + i * 264 + pxb) = t;
    }
    // ---- stage W: Wt[ch][j= o*3+kk], tf32-rounded ----
    for (int v = tid; v < 12288; v += 256) {
        int o = v / 192, rem = v - o * 192;
        int i = rem / 3, kk = rem - i * 3;
        Wt[i * 200 + o * 3 + kk] = tf32r(cw[v]);
    }
    __syncthreads();

    const float* sM1 = sC;
    const float* sM2 = sC + 64;
    const float* sA1 = sC + 128;
    const float* sA6 = sC + 136;
    const float* sA7 = sC + 144;
    const float* sG  = sC + 152;

    const int mg = wid & 3;          // m-group: px0 = mg*64
    const int ng = wid >> 2;         // n-group: local j base = ng*24
    const int px0 = mg * 64;
    const int jb = ng * 24;

    for (int oc = 0; oc < 4; oc++) {
        // ---- GEMM: Z[px][j] for j in [oc*48, oc*48+48) ----
        {
            float acc[4][3][4];
            #pragma unroll
            for (int t = 0; t < 4; t++)
                #pragma unroll
                for (int nt = 0; nt < 3; nt++)
                    #pragma unroll
                    for (int e = 0; e < 4; e++) acc[t][nt][e] = 0.f;

            #pragma unroll 2
            for (int k8 = 0; k8 < 8; k8++) {
                const int k0 = k8 * 8;
                const float* Xc0 = Xs2 + (k0 + c) * 264 + px0 + g;
                const float* Xc4 = Xc0 + 4 * 264;
                float a[4][4];
                #pragma unroll
                for (int t = 0; t < 4; t++) {
                    a[t][0] = Xc0[16 * t];
                    a[t][1] = Xc0[16 * t + 8];
                    a[t][2] = Xc4[16 * t];
                    a[t][3] = Xc4[16 * t + 8];
                }
                const float* Wc0 = Wt + (k0 + c) * 200 + oc * 48 + jb + g;
                const float* Wc4 = Wc0 + 4 * 200;
                float b[3][2];
                #pragma unroll
                for (int nt = 0; nt < 3; nt++) {
                    b[nt][0] = Wc0[8 * nt];
                    b[nt][1] = Wc4[8 * nt];
                }
                #pragma unroll
                for (int t = 0; t < 4; t++)
                    #pragma unroll
                    for (int nt = 0; nt < 3; nt++)
                        mma_tf32(acc[t][nt], a[t], b[nt]);
            }
            // D-frag store: d0=(g,2c), d1=(g,2c+1), d2=(g+8,2c), d3=(g+8,2c+1)
            #pragma unroll
            for (int t = 0; t < 4; t++)
                #pragma unroll
                for (int nt = 0; nt < 3; nt++) {
                    int jl = jb + nt * 8 + 2 * c;
                    int pxb = px0 + 16 * t + g;
                    Zb[jl * 268 + pxb]           = acc[t][nt][0];
                    Zb[(jl + 1) * 268 + pxb]     = acc[t][nt][1];
                    Zb[jl * 268 + pxb + 8]       = acc[t][nt][2];
                    Zb[(jl + 1) * 268 + pxb + 8] = acc[t][nt][3];
                }
        }
        __syncthreads();

        // ---- Tsum: per (u,B): which0 = row-sums z1, which1 = row-sums z2, which2 = dot(z2, a1) ----
        {
            float4 a1a = *(const float4*)sA1;
            float4 a1b = *(const float4*)(sA1 + 4);
            #pragma unroll
            for (int vv = 0; vv < 6; vv++) {
                int v = tid + 256 * vv;          // 1536 values
                int s = v & 7;
                int t2 = v >> 3;
                int which = t2 % 3;
                int ub = t2 / 3;                 // u*4 + B
                int jrow = (ub >> 2) * 3 + ((which == 0) ? 1 : 2);
                const float* zr = Zb + jrow * 268 + (ub & 3) * 64 + s * 8;
                float4 za = *(const float4*)zr;
                float4 zc = *(const float4*)(zr + 4);
                float acc;
                if (which == 2)
                    acc = dot4(za, a1a) + dot4(zc, a1b);
                else
                    acc = za.x + za.y + za.z + za.w + zc.x + zc.y + zc.z + zc.w;
                Ts[ub * 24 + which * 8 + s] = acc;
            }
        }
        __syncthreads();

        // ---- Phase B: spatial epilogue, 2 units per thread ----
        #pragma unroll
        for (int un = 0; un < 2; un++) {
            int unit = tid + 256 * un;           // 512 units: (u, B, r)
            int u = unit >> 5;
            int B = (unit >> 3) & 3;
            int r = unit & 7;
            const float* z0p = Zb + (u * 3) * 268 + B * 64 + r * 8;
            float4 z0a = *(const float4*)z0p,          z0b = *(const float4*)(z0p + 4);
            float4 z1a = *(const float4*)(z0p + 268),  z1b = *(const float4*)(z0p + 272);
            float4 z2a = *(const float4*)(z0p + 536),  z2b = *(const float4*)(z0p + 540);
            const float* ts = Ts + (u * 4 + B) * 24;
            float4 t0a = *(const float4*)ts,        t0b = *(const float4*)(ts + 4);
            float4 t1a = *(const float4*)(ts + 8),  t1b = *(const float4*)(ts + 12);
            float4 t2a = *(const float4*)(ts + 16), t2b = *(const float4*)(ts + 20);
            float4 m1ra = *(const float4*)(sM1 + r * 8);
            float4 m1rb = *(const float4*)(sM1 + r * 8 + 4);

            float w1 = dot4(m1ra, t0a) + dot4(m1rb, t0b);
            float w2 = dot4(m1ra, t1a) + dot4(m1rb, t1b);
            float w3 = dot4(m1ra, t2a) + dot4(m1rb, t2b);

            const int o = oc * 16 + u;
            const float bias = __ldg(cb + o);
            const float inv_s8 = 0.3535533905932738f;  // 1/sqrt(8)
            const float wa7 = w1 * inv_s8 + w3;
            const float wa6 = w2 * inv_s8;
            const float gb  = bias * sG[r];

            float a[8];
            #pragma unroll
            for (int cc = 0; cc < 8; cc++) {
                float4 m1a = *(const float4*)(sM1 + cc * 8);
                float4 m1b = *(const float4*)(sM1 + cc * 8 + 4);
                float4 m2a = *(const float4*)(sM2 + cc * 8);
                float4 m2b = *(const float4*)(sM2 + cc * 8 + 4);
                float v = ((const float*)&z0a)[0];  // placeholder avoided below
                v = (cc < 4 ? ((const float*)&z0a)[cc] : ((const float*)&z0b)[cc - 4]);
                v += dot4(m1a, z1a) + dot4(m1b, z1b);
                v += dot4(m2a, z2a) + dot4(m2b, z2b);
                v += wa7 * sA7[cc] + wa6 * sA6[cc] + gb * sG[cc];
                a[cc] = v;
            }

            float* outp = out + (bb * 64 + o) * (size_t)65536
                              + (size_t)(y0 + r) * 256 + x0 + B * 8;
            *(float4*)outp       = make_float4(a[0], a[1], a[2], a[3]);
            *(float4*)(outp + 4) = make_float4(a[4], a[5], a[6], a[7]);
        }
        __syncthreads();
    }
}

extern "C" void kernel_launch(void* const* d_in, const int* in_sizes, int n_in,
                              void* d_out, int out_size) {
    const float* x  = (const float*)d_in[0];
    const float* cw = (const float*)d_in[1];
    const float* cb = (const float*)d_in[2];
    float* out = (float*)d_out;
    (void)in_sizes; (void)n_in; (void)out_size;

    cudaFuncSetAttribute(dctconv_mma, cudaFuncAttributeMaxDynamicSharedMemorySize,
                         SM_FLOATS * (int)sizeof(float));

    init_consts_kernel<<<1, 192>>>();
    dim3 grid(8, 32, 8);   // (W/32, H/8, bsz)
    dctconv_mma<<<grid, 256, SM_FLOATS * sizeof(float)>>>(x, cw, cb, out);
}